// round 15
// baseline (speedup 1.0000x reference)
#include <cuda_runtime.h>
#include <cuda_fp16.h>
#include <cstdint>

// ---------------------------------------------------------------------------
// Problem constants
// ---------------------------------------------------------------------------
static constexpr int M = 4096;      // tokens
static constexpr int K = 4096;      // in_features
static constexpr int N = 11008;     // out_features
static constexpr int KP = K / 8;    // packed qweight rows

// GEMM tiling
static constexpr int BM = 128;
static constexpr int BN = 128;
static constexpr int BK = 64;
static constexpr int STAGES = 3;
static constexpr int NIT = K / BK;          // 64
static constexpr int LDS_T = 72;            // halves: 64 + 8 pad = 144B stride
static constexpr int A_HALFS = BM * LDS_T;  // 9216
static constexpr int STAGE_HALFS = (BM + BN) * LDS_T;  // 18432
static constexpr int STAGE_BYTES = STAGE_HALFS * 2;    // 36864
static constexpr int SMEM_BYTES = STAGES * STAGE_BYTES; // 110592

// fp16 scratch (static __device__ -- no allocation)
__device__ __half g_Wt[(size_t)N * K];   // W transposed: [N, K]
__device__ __half g_Xh[(size_t)M * K];   // x as fp16:    [M, K]

// ---------------------------------------------------------------------------
__device__ __forceinline__ uint32_t smem_u32(const void* p) {
    uint32_t a;
    asm("{ .reg .u64 t; cvta.to.shared.u64 t, %1; cvt.u32.u64 %0, t; }" : "=r"(a) : "l"(p));
    return a;
}
__device__ __forceinline__ void cp_async16(uint32_t dst, const void* src) {
    asm volatile("cp.async.cg.shared.global [%0], [%1], 16;" :: "r"(dst), "l"(src) : "memory");
}
__device__ __forceinline__ void cp_commit() {
    asm volatile("cp.async.commit_group;" ::: "memory");
}
__device__ __forceinline__ void cp_wait1() {
    asm volatile("cp.async.wait_group 1;" ::: "memory");
}
__device__ __forceinline__ void cp_wait0() {
    asm volatile("cp.async.wait_group 0;" ::: "memory");
}
__device__ __forceinline__ void ldsm_x4(uint32_t* r, uint32_t addr) {
    asm volatile("ldmatrix.sync.aligned.m8n8.x4.shared.b16 {%0,%1,%2,%3}, [%4];"
                 : "=r"(r[0]), "=r"(r[1]), "=r"(r[2]), "=r"(r[3]) : "r"(addr));
}
__device__ __forceinline__ void mma16816(float* c, const uint32_t* a, const uint32_t* b) {
    asm volatile("mma.sync.aligned.m16n8k16.row.col.f32.f16.f16.f32 "
                 "{%0,%1,%2,%3}, {%4,%5,%6,%7}, {%8,%9}, {%0,%1,%2,%3};"
                 : "+f"(c[0]), "+f"(c[1]), "+f"(c[2]), "+f"(c[3])
                 : "r"(a[0]), "r"(a[1]), "r"(a[2]), "r"(a[3]), "r"(b[0]), "r"(b[1]));
}

// ---------------------------------------------------------------------------
// Fused prep: blocks [0, 8192): x f32 -> g_Xh fp16 ; rest: dequant -> g_Wt
// ---------------------------------------------------------------------------
static constexpr int CONV_BLOCKS = (int)((size_t)M * K / 8 / 256);  // 8192
__global__ void prep_kernel(const float* __restrict__ x,
                            const int* __restrict__ qweight,
                            const int* __restrict__ qzeros,
                            const float* __restrict__ scales,
                            const int* __restrict__ g_idx) {
    if (blockIdx.x < CONV_BLOCKS) {
        size_t base = ((size_t)blockIdx.x * 256 + threadIdx.x) * 8;
        float4 a = *(const float4*)&x[base];
        float4 b = *(const float4*)&x[base + 4];
        __half2 h[4];
        h[0] = __floats2half2_rn(a.x, a.y);
        h[1] = __floats2half2_rn(a.z, a.w);
        h[2] = __floats2half2_rn(b.x, b.y);
        h[3] = __floats2half2_rn(b.z, b.w);
        *(uint4*)&g_Xh[base] = *(uint4*)h;
    } else {
        int dq = blockIdx.x - CONV_BLOCKS;
        int bx = dq % (N / 32);
        int by = dq / (N / 32);
        int n  = bx * 32 + (threadIdx.x >> 3);
        int kk = by * 8  + (threadIdx.x & 7);

        int   g    = g_idx[kk * 8];
        int   qw   = qweight[(size_t)kk * N + n];
        int   qz   = qzeros[(size_t)g * (N / 8) + (n >> 3)];
        int   zero = ((qz >> ((n & 7) * 4)) & 15) + 1;
        float s    = scales[(size_t)g * N + n];

        __half h[8];
#pragma unroll
        for (int i = 0; i < 8; i++) {
            int w = ((qw >> (4 * i)) & 15) - zero;
            h[i] = __float2half(s * (float)w);
        }
        *(uint4*)&g_Wt[(size_t)n * K + kk * 8] = *(uint4*)h;
    }
}

// ---------------------------------------------------------------------------
// GEMM: C[M,N] = g_Xh[M,K] @ g_Wt[N,K]^T + bias.
// 128x128 CTA, BK=64, 3-stage cp.async, 256 threads = 8 warps (2Mx4N),
// warp tile 64x32, single-buffered frags, 2 CTAs/SM -> 4 warps/SMSP.
// SLICE ROTATION: warp w walks k-slices in order (s+w)&3, de-correlating
// LDSM bursts across warps so the tensor pipe is fed continuously.
// ---------------------------------------------------------------------------
__global__ __launch_bounds__(256, 2)
void gemm_kernel(const float* __restrict__ bias, float* __restrict__ C) {
    extern __shared__ __half smem[];
    const uint32_t sbase = smem_u32(smem);

    const int tid  = threadIdx.x;
    const int warp = tid >> 5;
    const int lane = tid & 31;
    const int wm   = (warp >> 2) * 64;   // 2 warp rows of 64
    const int wn   = (warp & 3) * 32;    // 4 warp cols of 32

    const int bm = blockIdx.y * BM;
    const int bn = blockIdx.x * BN;

    // ---- cp.async mapping: 2048 x 16B chunks/stage, 8 per thread ----
    const int r0 = tid >> 3;            // 0..31
    const int c0 = tid & 7;             // chunk in 128B data row
    const __half* gA = g_Xh + (size_t)(bm + r0) * K + c0 * 8;
    const __half* gB = g_Wt + (size_t)(bn + r0) * K + c0 * 8;
    const uint32_t dA = (uint32_t)(r0 * LDS_T + c0 * 8) * 2;
    const uint32_t dB = dA + A_HALFS * 2;

    // ---- ldmatrix lane address components (within a stage, in bytes) ----
    const uint32_t aRow  = (uint32_t)(wm + (lane & 15));
    const uint32_t aColX = (uint32_t)((lane >> 4) * 8);
    const uint32_t aBase = sbase + (aRow * LDS_T + aColX) * 2;
    const uint32_t bRow  = (uint32_t)(wn + (lane & 7) + ((lane >> 4) << 3));
    const uint32_t bColX = (uint32_t)(((lane >> 3) & 1) * 8);
    const uint32_t bBase = sbase + A_HALFS * 2 + (bRow * LDS_T + bColX) * 2;

    float acc[4][4][4];   // mi x nj(8col) x 4
#pragma unroll
    for (int i = 0; i < 4; i++)
#pragma unroll
        for (int j = 0; j < 4; j++)
#pragma unroll
            for (int t = 0; t < 4; t++)
                acc[i][j][t] = 0.0f;

    // ---- prologue: issue stages 0..1 ----
#pragma unroll
    for (int s = 0; s < STAGES - 1; s++) {
        const uint32_t st = sbase + (uint32_t)s * STAGE_BYTES;
        const size_t ko = (size_t)s * BK;
#pragma unroll
        for (int l = 0; l < 4; l++) {
            cp_async16(st + dA + l * 32 * LDS_T * 2, gA + (size_t)l * 32 * K + ko);
            cp_async16(st + dB + l * 32 * LDS_T * 2, gB + (size_t)l * 32 * K + ko);
        }
        cp_commit();
    }

    // per-warp rotated slice byte-offsets
    uint32_t koff[4];
#pragma unroll
    for (int s = 0; s < 4; s++)
        koff[s] = (uint32_t)(((s + warp) & 3) * 16) * 2;

    for (int i = 0; i < NIT; i++) {
        cp_wait1();
        __syncthreads();

        const uint32_t so = (uint32_t)(i % STAGES) * STAGE_BYTES;
        const uint32_t aB = aBase + so;
        const uint32_t bB = bBase + so;

        // issue next-stage cp.async first (overlaps compute below)
        const int p = i + STAGES - 1;
        if (p < NIT) {
            const uint32_t st = sbase + (uint32_t)(p % STAGES) * STAGE_BYTES;
            const size_t ko = (size_t)p * BK;
#pragma unroll
            for (int l = 0; l < 4; l++) {
                cp_async16(st + dA + l * 32 * LDS_T * 2, gA + (size_t)l * 32 * K + ko);
                cp_async16(st + dB + l * 32 * LDS_T * 2, gB + (size_t)l * 32 * K + ko);
            }
        }
        cp_commit();

        // 4 k-slices in per-warp rotated order
#pragma unroll
        for (int s = 0; s < 4; s++) {
            const uint32_t ks = koff[s];
            uint32_t a[4][4], b[2][4];
#pragma unroll
            for (int mi = 0; mi < 4; mi++)
                ldsm_x4(a[mi], aB + (mi * 16 * LDS_T) * 2 + ks);
#pragma unroll
            for (int nj = 0; nj < 2; nj++)
                ldsm_x4(b[nj], bB + (nj * 16 * LDS_T) * 2 + ks);
#pragma unroll
            for (int mi = 0; mi < 4; mi++)
#pragma unroll
                for (int nj = 0; nj < 2; nj++) {
                    mma16816(acc[mi][nj * 2 + 0], a[mi], &b[nj][0]);
                    mma16816(acc[mi][nj * 2 + 1], a[mi], &b[nj][2]);
                }
        }
    }
    cp_wait0();

    // ---- epilogue: direct register -> global, fused bias ----
    const int erow = lane >> 2;
    const int ecol = (lane & 3) * 2;
    float2 bb[4];
#pragma unroll
    for (int nj = 0; nj < 4; nj++)
        bb[nj] = *(const float2*)&bias[bn + wn + nj * 8 + ecol];

#pragma unroll
    for (int mi = 0; mi < 4; mi++) {
        const int gm0 = bm + wm + mi * 16 + erow;
#pragma unroll
        for (int nj = 0; nj < 4; nj++) {
            const int gn = bn + wn + nj * 8 + ecol;
            float2 v0, v1;
            v0.x = acc[mi][nj][0] + bb[nj].x;
            v0.y = acc[mi][nj][1] + bb[nj].y;
            v1.x = acc[mi][nj][2] + bb[nj].x;
            v1.y = acc[mi][nj][3] + bb[nj].y;
            *(float2*)&C[(size_t)gm0 * N + gn] = v0;
            *(float2*)&C[(size_t)(gm0 + 8) * N + gn] = v1;
        }
    }
}

// ---------------------------------------------------------------------------
extern "C" void kernel_launch(void* const* d_in, const int* in_sizes, int n_in,
                              void* d_out, int out_size) {
    const float* x       = (const float*)d_in[0];
    const int*   qweight = (const int*)d_in[1];
    const int*   qzeros  = (const int*)d_in[2];
    const float* scales  = (const float*)d_in[3];
    const int*   g_idx   = (const int*)d_in[4];
    const float* bias    = (const float*)d_in[5];
    float*       out     = (float*)d_out;

    cudaFuncSetAttribute(gemm_kernel,
                         cudaFuncAttributeMaxDynamicSharedMemorySize, SMEM_BYTES);

    int prep_blocks = CONV_BLOCKS + (N / 32) * (KP / 8);
    prep_kernel<<<prep_blocks, 256>>>(x, qweight, qzeros, scales, g_idx);

    dim3 gemm_grid(N / BN, M / BM);   // 86 x 32
    gemm_kernel<<<gemm_grid, 256, SMEM_BYTES>>>(bias, out);
}

// round 16
// speedup vs baseline: 1.0540x; 1.0540x over previous
#include <cuda_runtime.h>
#include <cuda_fp16.h>
#include <cstdint>

// ---------------------------------------------------------------------------
// Problem constants
// ---------------------------------------------------------------------------
static constexpr int M = 4096;      // tokens
static constexpr int K = 4096;      // in_features
static constexpr int N = 11008;     // out_features
static constexpr int KP = K / 8;    // packed qweight rows

// GEMM tiling (R7/R14 proven config)
static constexpr int BM = 128;
static constexpr int BN = 128;
static constexpr int BK = 64;
static constexpr int STAGES = 3;
static constexpr int NIT = K / BK;          // 64
static constexpr int LDS_T = 72;            // halves: 64 + 8 pad = 144B stride
static constexpr int A_HALFS = BM * LDS_T;  // 9216
static constexpr int STAGE_HALFS = (BM + BN) * LDS_T;  // 18432
static constexpr int STAGE_BYTES = STAGE_HALFS * 2;    // 36864
static constexpr int SMEM_BYTES = STAGES * STAGE_BYTES; // 110592

// epilogue staging: per warp 64 rows x 68 f32 (272B stride) = 17408B
static constexpr int EP_T = 68;
static constexpr int EP_WARP_BYTES = 64 * EP_T * 4;    // 17408

// raster swizzle: panels of 16 m-blocks; within a panel bm varies fastest
static constexpr int GN = N / BN;           // 86
static constexpr int PANEL_M = 16;
static constexpr int PANEL_CTAS = PANEL_M * GN;  // 1376

// fp16 scratch (static __device__ -- no allocation)
__device__ __half g_Wt[(size_t)N * K];   // W transposed: [N, K]
__device__ __half g_Xh[(size_t)M * K];   // x as fp16:    [M, K]

// ---------------------------------------------------------------------------
__device__ __forceinline__ uint32_t smem_u32(const void* p) {
    uint32_t a;
    asm("{ .reg .u64 t; cvta.to.shared.u64 t, %1; cvt.u32.u64 %0, t; }" : "=r"(a) : "l"(p));
    return a;
}
__device__ __forceinline__ void cp_async16(uint32_t dst, const void* src) {
    asm volatile("cp.async.cg.shared.global [%0], [%1], 16;" :: "r"(dst), "l"(src) : "memory");
}
__device__ __forceinline__ void cp_commit() {
    asm volatile("cp.async.commit_group;" ::: "memory");
}
__device__ __forceinline__ void cp_wait1() {
    asm volatile("cp.async.wait_group 1;" ::: "memory");
}
__device__ __forceinline__ void cp_wait0() {
    asm volatile("cp.async.wait_group 0;" ::: "memory");
}
__device__ __forceinline__ void ldsm_x4(uint32_t* r, uint32_t addr) {
    asm volatile("ldmatrix.sync.aligned.m8n8.x4.shared.b16 {%0,%1,%2,%3}, [%4];"
                 : "=r"(r[0]), "=r"(r[1]), "=r"(r[2]), "=r"(r[3]) : "r"(addr));
}
__device__ __forceinline__ void mma16816(float* c, const uint32_t* a, const uint32_t* b) {
    asm volatile("mma.sync.aligned.m16n8k16.row.col.f32.f16.f16.f32 "
                 "{%0,%1,%2,%3}, {%4,%5,%6,%7}, {%8,%9}, {%0,%1,%2,%3};"
                 : "+f"(c[0]), "+f"(c[1]), "+f"(c[2]), "+f"(c[3])
                 : "r"(a[0]), "r"(a[1]), "r"(a[2]), "r"(a[3]), "r"(b[0]), "r"(b[1]));
}
__device__ __forceinline__ void sts_64(uint32_t addr, float x, float y) {
    asm volatile("st.shared.v2.f32 [%0], {%1,%2};" :: "r"(addr), "f"(x), "f"(y) : "memory");
}
__device__ __forceinline__ void lds_128(uint32_t addr, float* v) {
    asm volatile("ld.shared.v4.f32 {%0,%1,%2,%3}, [%4];"
                 : "=f"(v[0]), "=f"(v[1]), "=f"(v[2]), "=f"(v[3]) : "r"(addr));
}

// ---------------------------------------------------------------------------
// Fused prep: blocks [0, 8192): x f32 -> g_Xh fp16 ; rest: dequant -> g_Wt
// ---------------------------------------------------------------------------
static constexpr int CONV_BLOCKS = (int)((size_t)M * K / 8 / 256);  // 8192
__global__ void prep_kernel(const float* __restrict__ x,
                            const int* __restrict__ qweight,
                            const int* __restrict__ qzeros,
                            const float* __restrict__ scales,
                            const int* __restrict__ g_idx) {
    if (blockIdx.x < CONV_BLOCKS) {
        size_t base = ((size_t)blockIdx.x * 256 + threadIdx.x) * 8;
        float4 a = *(const float4*)&x[base];
        float4 b = *(const float4*)&x[base + 4];
        __half2 h[4];
        h[0] = __floats2half2_rn(a.x, a.y);
        h[1] = __floats2half2_rn(a.z, a.w);
        h[2] = __floats2half2_rn(b.x, b.y);
        h[3] = __floats2half2_rn(b.z, b.w);
        *(uint4*)&g_Xh[base] = *(uint4*)h;
    } else {
        int dq = blockIdx.x - CONV_BLOCKS;
        int bx = dq % (N / 32);
        int by = dq / (N / 32);
        int n  = bx * 32 + (threadIdx.x >> 3);
        int kk = by * 8  + (threadIdx.x & 7);

        int   g    = g_idx[kk * 8];
        int   qw   = qweight[(size_t)kk * N + n];
        int   qz   = qzeros[(size_t)g * (N / 8) + (n >> 3)];
        int   zero = ((qz >> ((n & 7) * 4)) & 15) + 1;
        float s    = scales[(size_t)g * N + n];

        __half h[8];
#pragma unroll
        for (int i = 0; i < 8; i++) {
            int w = ((qw >> (4 * i)) & 15) - zero;
            h[i] = __float2half(s * (float)w);
        }
        *(uint4*)&g_Wt[(size_t)n * K + kk * 8] = *(uint4*)h;
    }
}

// ---------------------------------------------------------------------------
// GEMM: C[M,N] = g_Xh[M,K] @ g_Wt[N,K]^T + bias.
// R14 kernel (R7 mainloop + coalesced smem-staged epilogue) with a swizzled
// 1-D raster: concurrent CTAs cover a compact 16x~19 tile region so the
// per-wave L2 working set shrinks ~2.5x and W streams ~2 passes, not ~9.
// ---------------------------------------------------------------------------
__global__ __launch_bounds__(128, 2)
void gemm_kernel(const float* __restrict__ bias, float* __restrict__ C) {
    extern __shared__ __half smem[];
    const uint32_t sbase = smem_u32(smem);

    const int tid  = threadIdx.x;
    const int warp = tid >> 5;
    const int lane = tid & 31;
    const int wm   = (warp >> 1) * 64;   // warp M offset within CTA
    const int wn   = (warp & 1) * 64;    // warp N offset within CTA

    // ---- swizzled raster: panel of 16 m-blocks, bm fastest within panel ----
    const int lin   = blockIdx.x;
    const int panel = lin / PANEL_CTAS;
    const int rem   = lin - panel * PANEL_CTAS;
    const int bm    = (panel * PANEL_M + (rem & (PANEL_M - 1))) * BM;
    const int bn    = (rem >> 4) * BN;

    // ---- cp.async mapping: 2048 x 16B chunks/stage, 16 per thread ----
    const int r0 = tid >> 3;            // 0..15
    const int c0 = tid & 7;             // chunk in 128B data row
    const __half* gA = g_Xh + (size_t)(bm + r0) * K + c0 * 8;
    const __half* gB = g_Wt + (size_t)(bn + r0) * K + c0 * 8;
    const uint32_t dA = (uint32_t)(r0 * LDS_T + c0 * 8) * 2;
    const uint32_t dB = dA + A_HALFS * 2;

    // ---- ldmatrix lane address components (within a stage, in bytes) ----
    const uint32_t aRow  = (uint32_t)(wm + (lane & 15));
    const uint32_t aColX = (uint32_t)((lane >> 4) * 8);
    const uint32_t aBase = sbase + (aRow * LDS_T + aColX) * 2;
    const uint32_t bRow  = (uint32_t)(wn + (lane & 7) + ((lane >> 4) << 3));
    const uint32_t bColX = (uint32_t)(((lane >> 3) & 1) * 8);
    const uint32_t bBase = sbase + A_HALFS * 2 + (bRow * LDS_T + bColX) * 2;

    float acc[4][8][4];
#pragma unroll
    for (int i = 0; i < 4; i++)
#pragma unroll
        for (int j = 0; j < 8; j++)
#pragma unroll
            for (int t = 0; t < 4; t++)
                acc[i][j][t] = 0.0f;

    // ---- prologue: issue stages 0..1 ----
#pragma unroll
    for (int s = 0; s < STAGES - 1; s++) {
        const uint32_t st = sbase + (uint32_t)s * STAGE_BYTES;
        const size_t ko = (size_t)s * BK;
#pragma unroll
        for (int l = 0; l < 8; l++) {
            cp_async16(st + dA + l * 16 * LDS_T * 2, gA + (size_t)l * 16 * K + ko);
            cp_async16(st + dB + l * 16 * LDS_T * 2, gB + (size_t)l * 16 * K + ko);
        }
        cp_commit();
    }

    uint32_t a[2][4][4], b[2][4][4];

    for (int i = 0; i < NIT; i++) {
        cp_wait1();
        __syncthreads();

        const uint32_t so = (uint32_t)(i % STAGES) * STAGE_BYTES;

        // load k-slice 0 fragments (critical path) first
#pragma unroll
        for (int mi = 0; mi < 4; mi++)
            ldsm_x4(a[0][mi], aBase + so + (mi * 16 * LDS_T) * 2);
#pragma unroll
        for (int nj = 0; nj < 4; nj++)
            ldsm_x4(b[0][nj], bBase + so + (nj * 16 * LDS_T) * 2);

        // issue next-stage cp.async early (overlaps compute below)
        const int p = i + STAGES - 1;
        if (p < NIT) {
            const uint32_t st = sbase + (uint32_t)(p % STAGES) * STAGE_BYTES;
            const size_t ko = (size_t)p * BK;
#pragma unroll
            for (int l = 0; l < 8; l++) {
                cp_async16(st + dA + l * 16 * LDS_T * 2, gA + (size_t)l * 16 * K + ko);
                cp_async16(st + dB + l * 16 * LDS_T * 2, gB + (size_t)l * 16 * K + ko);
            }
        }
        cp_commit();

        // 4 k-slices, double-buffered frags
#pragma unroll
        for (int s = 0; s < 4; s++) {
            const int cur = s & 1, nxt = cur ^ 1;
            if (s < 3) {
                const uint32_t ks = (uint32_t)(s + 1) * 16 * 2;
#pragma unroll
                for (int mi = 0; mi < 4; mi++)
                    ldsm_x4(a[nxt][mi], aBase + so + (mi * 16 * LDS_T) * 2 + ks);
#pragma unroll
                for (int nj = 0; nj < 4; nj++)
                    ldsm_x4(b[nxt][nj], bBase + so + (nj * 16 * LDS_T) * 2 + ks);
            }
#pragma unroll
            for (int mi = 0; mi < 4; mi++) {
#pragma unroll
                for (int nj = 0; nj < 4; nj++) {
                    mma16816(acc[mi][nj * 2 + 0], a[cur][mi], &b[cur][nj][0]);
                    mma16816(acc[mi][nj * 2 + 1], a[cur][mi], &b[cur][nj][2]);
                }
            }
        }
    }
    cp_wait0();
    __syncthreads();   // all warps done with pipeline smem before reuse

    // ---- epilogue: stage acc to smem, write coalesced 256B row segments ----
    {
        const uint32_t ebase = sbase + (uint32_t)warp * EP_WARP_BYTES;

        const int erow = lane >> 2;          // 0..7
        const int ecol = (lane & 3) * 2;     // 0,2,4,6
#pragma unroll
        for (int mi = 0; mi < 4; mi++) {
#pragma unroll
            for (int nj = 0; nj < 8; nj++) {
                const uint32_t ad0 = ebase
                    + (uint32_t)((mi * 16 + erow) * EP_T + nj * 8 + ecol) * 4;
                sts_64(ad0, acc[mi][nj][0], acc[mi][nj][1]);
                sts_64(ad0 + 8 * EP_T * 4, acc[mi][nj][2], acc[mi][nj][3]);
            }
        }
        __syncwarp();

        const int trow = lane >> 4;          // 0..1
        const int tcol = (lane & 15) * 4;    // f32 col 0..60
        const int gn   = bn + wn + tcol;
        float4 b4 = *(const float4*)&bias[gn];

#pragma unroll
        for (int rr = 0; rr < 32; rr++) {
            const int row = rr * 2 + trow;
            float v[4];
            lds_128(ebase + (uint32_t)(row * EP_T + tcol) * 4, v);
            float4 o;
            o.x = v[0] + b4.x;
            o.y = v[1] + b4.y;
            o.z = v[2] + b4.z;
            o.w = v[3] + b4.w;
            *(float4*)&C[(size_t)(bm + wm + row) * N + gn] = o;
        }
    }
}

// ---------------------------------------------------------------------------
extern "C" void kernel_launch(void* const* d_in, const int* in_sizes, int n_in,
                              void* d_out, int out_size) {
    const float* x       = (const float*)d_in[0];
    const int*   qweight = (const int*)d_in[1];
    const int*   qzeros  = (const int*)d_in[2];
    const float* scales  = (const float*)d_in[3];
    const int*   g_idx   = (const int*)d_in[4];
    const float* bias    = (const float*)d_in[5];
    float*       out     = (float*)d_out;

    cudaFuncSetAttribute(gemm_kernel,
                         cudaFuncAttributeMaxDynamicSharedMemorySize, SMEM_BYTES);

    int prep_blocks = CONV_BLOCKS + (N / 32) * (KP / 8);
    prep_kernel<<<prep_blocks, 256>>>(x, qweight, qzeros, scales, g_idx);

    gemm_kernel<<<(M / BM) * (N / BN), 128, SMEM_BYTES>>>(bias, out);
}